// round 12
// baseline (speedup 1.0000x reference)
#include <cuda_runtime.h>
#include <cuda_fp16.h>
#include <cstdint>
#include <cstddef>

static constexpr int TOKENS = 8192;
static constexpr int INF    = 4096;
static constexpr int NF     = 4096;
static constexpr int RDIM   = 256;
static constexpr int KSEL   = 128;

__device__ __align__(16) uint16_t g_A[(size_t)TOKENS * INF];  // x fp16 [M][K]
__device__ __align__(16) uint16_t g_W[(size_t)NF * INF];      // W fp16 [N][K]

__device__ __forceinline__ uint32_t smem_u32(const void* p) {
    uint32_t a;
    asm("{ .reg .u64 t; cvta.to.shared.u64 t, %1; cvt.u32.u64 %0, t; }"
        : "=r"(a) : "l"(p));
    return a;
}

__device__ __forceinline__ void cp_async16(uint32_t dst, const void* src) {
    asm volatile("cp.async.cg.shared.global [%0], [%1], 16;"
                 :: "r"(dst), "l"(src) : "memory");
}

__device__ __forceinline__ uint32_t sw128(uint32_t off) {
    return off ^ ((off >> 3) & 0x70u);
}

__device__ __forceinline__ void mbar_init(uint32_t a, uint32_t c) {
    asm volatile("mbarrier.init.shared.b64 [%0], %1;" :: "r"(a), "r"(c) : "memory");
}

__device__ __forceinline__ void mbar_arrive(uint32_t a) {
    asm volatile("mbarrier.arrive.shared.b64 _, [%0];" :: "r"(a) : "memory");
}

__device__ __forceinline__ void mbar_wait(uint32_t a, uint32_t parity) {
    asm volatile(
        "{\n\t.reg .pred P1;\n\t"
        "W_%=:\n\t"
        "mbarrier.try_wait.parity.acquire.cta.shared::cta.b64 P1, [%0], %1, 0x989680;\n\t"
        "@P1 bra.uni D_%=;\n\t"
        "bra.uni W_%=;\n\t"
        "D_%=:\n\t}" :: "r"(a), "r"(parity) : "memory");
}

__device__ __forceinline__ void cp_async_arrive(uint32_t mbar) {
    asm volatile("cp.async.mbarrier.arrive.noinc.shared.b64 [%0];"
                 :: "r"(mbar) : "memory");
}

#define LDMATRIX_X4(r0, r1, r2, r3, addr) \
    asm volatile("ldmatrix.sync.aligned.m8n8.x4.shared.b16 {%0,%1,%2,%3}, [%4];" \
                 : "=r"(r0), "=r"(r1), "=r"(r2), "=r"(r3) : "r"(addr))

#define MMA16816(c, a0, a1, a2, a3, b0, b1) \
    asm volatile("mma.sync.aligned.m16n8k16.row.col.f32.f16.f16.f32 " \
                 "{%0,%1,%2,%3}, {%4,%5,%6,%7}, {%8,%9}, {%0,%1,%2,%3};" \
                 : "+f"((c)[0]), "+f"((c)[1]), "+f"((c)[2]), "+f"((c)[3]) \
                 : "r"(a0), "r"(a1), "r"(a2), "r"(a3), "r"(b0), "r"(b1))

// --- Kernel 1: fp32 x -> fp16 g_A ---
__global__ void convert_x_kernel(const float* __restrict__ x) {
    size_t t = (size_t)blockIdx.x * blockDim.x + threadIdx.x;
    const float4* in4 = reinterpret_cast<const float4*>(x);
    float4 a = in4[2 * t], b = in4[2 * t + 1];
    __half2 h0 = __floats2half2_rn(a.x, a.y), h1 = __floats2half2_rn(a.z, a.w);
    __half2 h2 = __floats2half2_rn(b.x, b.y), h3 = __floats2half2_rn(b.z, b.w);
    uint4 u;
    u.x = *reinterpret_cast<uint32_t*>(&h0);
    u.y = *reinterpret_cast<uint32_t*>(&h1);
    u.z = *reinterpret_cast<uint32_t*>(&h2);
    u.w = *reinterpret_cast<uint32_t*>(&h3);
    reinterpret_cast<uint4*>(g_A)[t] = u;
}

// --- Kernel 2: parallel deterministic scatter, c-split of 4 ---
__global__ void __launch_bounds__(256)
scatter_w_kernel(const float* __restrict__ values,
                 const int* __restrict__ colidx) {
    extern __shared__ char sws[];
    float* acc = reinterpret_cast<float*>(sws);          // 64*256 floats
    int*   cols = reinterpret_cast<int*>(sws + 65536);   // 128 ints
    const int r = blockIdx.x >> 2, clo = (blockIdx.x & 3) * 64;
    const int t = threadIdx.x;
    if (t < KSEL) cols[t] = colidx[r * KSEL + t];
#pragma unroll
    for (int j = 0; j < 64; j++) acc[j * 256 + t] = 0.0f;
    __syncthreads();

    const float* vb = values + (size_t)r * (KSEL * 256) + t;
#pragma unroll 4
    for (int k = 0; k < KSEL; k++) {
        const int c = cols[k] - clo;
        if ((unsigned)c < 64u) acc[c * 256 + t] += __ldg(vb + (size_t)k * 256);
    }
    __syncthreads();

    const int o = t >> 4, i = t & 15;
    uint16_t* wr = g_W + (size_t)(r * 16 + o) * INF + i;
#pragma unroll
    for (int cc = 0; cc < 64; cc++)
        wr[(clo + cc) * 16] = __half_as_ushort(__float2half_rn(acc[cc * 256 + t]));
}

// --- Kernel 3: role-merged decoupled mma.sync fp16 GEMM ---
// CTA 128x256; 16 warps (4x4 of 32x64 tiles, 4/SMSP). Every thread both
// loads (6 cp.async/chunk, per-warp producer cursor) and computes (per-warp
// consumer cursor). 4 stages x 48 KB, per-stage mbarriers, NO CTA barrier.
static constexpr int STAGES      = 4;
static constexpr int A_BYTES     = 128 * 128;             // 16 KB
static constexpr int B_BYTES     = 256 * 128;             // 32 KB
static constexpr int STAGE_BYTES = A_BYTES + B_BYTES;     // 48 KB
static constexpr int GEMM_SMEM   = 1024 + STAGES * STAGE_BYTES;  // ~193 KB
static constexpr int NCHUNK      = INF / 64;              // 64

#define LOAD_CHUNK(stage, chunk) do {                                    \
    const uint32_t _ab = tb + (uint32_t)(stage) * STAGE_BYTES;           \
    const uint32_t _bb = _ab + A_BYTES;                                  \
    const int _koff = (chunk) * 64;                                      \
    cp_async16(_ab + sw0, asrc0 + _koff);                                \
    cp_async16(_ab + sw0 + 8192u, asrc0 + (size_t)64 * INF + _koff);     \
    _Pragma("unroll")                                                    \
    for (int _j = 0; _j < 4; _j++)                                       \
        cp_async16(_bb + sw0 + (uint32_t)_j * 8192u,                     \
                   bsrc0 + (size_t)_j * 64 * INF + _koff);               \
} while (0)

__global__ void __launch_bounds__(512, 1)
gemm_f16_kernel(float* __restrict__ out) {
    extern __shared__ char smem[];
    const uint32_t sb = smem_u32(smem);
    const uint32_t tb = sb + 1024;
    const int tid = threadIdx.x, wid = tid >> 5, lid = tid & 31;
    const int wm = wid >> 2, wn = wid & 3;  // 4(m) x 4(n) warp grid

    // full[s] = sb+16s (512 per-thread async arrivals),
    // empty[s] = sb+16s+8 (16 per-warp arrivals)
    if (tid == 0) {
#pragma unroll
        for (int s = 0; s < STAGES; s++) {
            mbar_init(sb + 16 * s, 512u);
            mbar_init(sb + 16 * s + 8, 16u);
        }
    }
    __syncthreads();

    const int m0 = blockIdx.y * 128, n0 = blockIdx.x * 256;

    // per-thread load plan: 6 x 16B per chunk, row stride 64 (row&7 invariant)
    const int row0 = tid >> 3, seg = tid & 7;
    const uint32_t sw0 = sw128((uint32_t)row0 * 128u + (uint32_t)seg * 16u);
    const uint16_t* asrc0 = g_A + (size_t)(m0 + row0) * INF + seg * 8;
    const uint16_t* bsrc0 = g_W + (size_t)(n0 + row0) * INF + seg * 8;

    // prologue: fill stages 0..S-2 (fresh stages, no empty wait needed)
#pragma unroll
    for (int j = 0; j < STAGES - 1; j++) {
        LOAD_CHUNK(j, j);
        cp_async_arrive(sb + 16 * j);
    }

    float acc[2][8][4];
#pragma unroll
    for (int mt = 0; mt < 2; mt++)
#pragma unroll
        for (int nt = 0; nt < 8; nt++)
#pragma unroll
            for (int q = 0; q < 4; q++) acc[mt][nt][q] = 0.0f;

    // sw128(row*128 + kb) = row*128 + (kb ^ ((lrow&7)<<4))
    const uint32_t lrow = (uint32_t)(lid & 15);
    const uint32_t lkb  = (uint32_t)(lid >> 4) * 16u;
    const uint32_t swb  = (lrow & 7u) << 4;
    uint32_t kbx[4];
#pragma unroll
    for (int ks = 0; ks < 4; ks++) kbx[ks] = ((uint32_t)ks * 32u + lkb) ^ swb;
    const uint32_t arow_off = ((uint32_t)(wm * 32) + lrow) * 128u;
    const uint32_t brow_off = ((uint32_t)(wn * 64) + lrow) * 128u;

    // cursors: consumer (cst,cph) from (0,0); producer (pst,pph) from (S-1,1)
    int cst = 0, pst = STAGES - 1;
    uint32_t cph = 0, pph = 1;

    for (int c = 0; c < NCHUNK; c++) {
        // produce chunk c+S-1 (stage freed once all warps consumed c-1)
        const int cl = c + STAGES - 1;
        if (cl < NCHUNK) {
            mbar_wait(sb + 16 * pst + 8, pph);
            LOAD_CHUNK(pst, cl);
            cp_async_arrive(sb + 16 * pst);
            if (++pst == STAGES) { pst = 0; pph ^= 1u; }
        }

        // consume chunk c
        mbar_wait(sb + 16 * cst, cph);

        const uint32_t ab = tb + (uint32_t)cst * STAGE_BYTES + arow_off;
        const uint32_t bb = tb + (uint32_t)cst * STAGE_BYTES + A_BYTES + brow_off;

#pragma unroll
        for (int ks = 0; ks < 4; ks++) {
            uint32_t bf[4][4];
#pragma unroll
            for (int j = 0; j < 4; j++)
                LDMATRIX_X4(bf[j][0], bf[j][1], bf[j][2], bf[j][3],
                            bb + (uint32_t)j * 2048u + kbx[ks]);
#pragma unroll
            for (int mt = 0; mt < 2; mt++) {
                uint32_t a0, a1, a2, a3;
                LDMATRIX_X4(a0, a1, a2, a3,
                            ab + (uint32_t)mt * 2048u + kbx[ks]);
#pragma unroll
                for (int j = 0; j < 4; j++) {
                    MMA16816(acc[mt][2 * j + 0], a0, a1, a2, a3, bf[j][0], bf[j][2]);
                    MMA16816(acc[mt][2 * j + 1], a0, a1, a2, a3, bf[j][1], bf[j][3]);
                }
            }
        }
        if (lid == 0) mbar_arrive(sb + 16 * cst + 8);  // release stage
        if (++cst == STAGES) { cst = 0; cph ^= 1u; }
    }

    // epilogue
    const int tq = lid >> 2, tr = lid & 3;
#pragma unroll
    for (int mt = 0; mt < 2; mt++) {
#pragma unroll
        for (int h = 0; h < 2; h++) {
            int gm = m0 + wm * 32 + mt * 16 + h * 8 + tq;
            float* row = out + (size_t)gm * NF + n0 + wn * 64 + tr * 2;
#pragma unroll
            for (int nt = 0; nt < 8; nt++) {
                float2 v;
                v.x = acc[mt][nt][h * 2 + 0];
                v.y = acc[mt][nt][h * 2 + 1];
                *reinterpret_cast<float2*>(row + nt * 8) = v;
            }
        }
    }
}

// --- pad: keeps the GEMM at ncu's sampled launch position ---
__global__ void pad_kernel() {}

extern "C" void kernel_launch(void* const* d_in, const int* in_sizes, int n_in,
                              void* d_out, int out_size) {
    const float* x      = (const float*)d_in[0];
    const float* values = (const float*)d_in[1];
    const int*   colidx = (const int*)d_in[2];
    float*       out    = (float*)d_out;

    cudaFuncSetAttribute(scatter_w_kernel,
                         cudaFuncAttributeMaxDynamicSharedMemorySize, 66048);
    cudaFuncSetAttribute(gemm_f16_kernel,
                         cudaFuncAttributeMaxDynamicSharedMemorySize, GEMM_SMEM);

    convert_x_kernel<<<16384, 256>>>(x);
    scatter_w_kernel<<<RDIM * 4, 256, 66048>>>(values, colidx);
    pad_kernel<<<1, 32>>>();
    dim3 grid(NF / 256, TOKENS / 128);  // (16, 64)
    gemm_f16_kernel<<<grid, 512, GEMM_SMEM>>>(out);
}

// round 13
// speedup vs baseline: 1.1164x; 1.1164x over previous
#include <cuda_runtime.h>
#include <cuda_fp16.h>
#include <cstdint>
#include <cstddef>

static constexpr int TOKENS = 8192;
static constexpr int INF    = 4096;
static constexpr int NF     = 4096;
static constexpr int RDIM   = 256;
static constexpr int KSEL   = 128;

__device__ __align__(16) uint16_t g_A[(size_t)TOKENS * INF];  // x fp16 [M][K]
__device__ __align__(16) uint16_t g_W[(size_t)NF * INF];      // W fp16 [N][K]

__device__ __forceinline__ uint32_t smem_u32(const void* p) {
    uint32_t a;
    asm("{ .reg .u64 t; cvta.to.shared.u64 t, %1; cvt.u32.u64 %0, t; }"
        : "=r"(a) : "l"(p));
    return a;
}

__device__ __forceinline__ void cp_async16(uint32_t dst, const void* src) {
    asm volatile("cp.async.cg.shared.global [%0], [%1], 16;"
                 :: "r"(dst), "l"(src) : "memory");
}

__device__ __forceinline__ uint32_t sw128(uint32_t off) {
    return off ^ ((off >> 3) & 0x70u);
}

__device__ __forceinline__ void mbar_init(uint32_t a, uint32_t c) {
    asm volatile("mbarrier.init.shared.b64 [%0], %1;" :: "r"(a), "r"(c) : "memory");
}

__device__ __forceinline__ void mbar_arrive(uint32_t a) {
    asm volatile("mbarrier.arrive.shared.b64 _, [%0];" :: "r"(a) : "memory");
}

__device__ __forceinline__ void mbar_wait(uint32_t a, uint32_t parity) {
    asm volatile(
        "{\n\t.reg .pred P1;\n\t"
        "W_%=:\n\t"
        "mbarrier.try_wait.parity.acquire.cta.shared::cta.b64 P1, [%0], %1, 0x989680;\n\t"
        "@P1 bra.uni D_%=;\n\t"
        "bra.uni W_%=;\n\t"
        "D_%=:\n\t}" :: "r"(a), "r"(parity) : "memory");
}

__device__ __forceinline__ void cp_async_arrive(uint32_t mbar) {
    asm volatile("cp.async.mbarrier.arrive.noinc.shared.b64 [%0];"
                 :: "r"(mbar) : "memory");
}

#define LDMATRIX_X4(r0, r1, r2, r3, addr) \
    asm volatile("ldmatrix.sync.aligned.m8n8.x4.shared.b16 {%0,%1,%2,%3}, [%4];" \
                 : "=r"(r0), "=r"(r1), "=r"(r2), "=r"(r3) : "r"(addr))

#define MMA16816(c, a0, a1, a2, a3, b0, b1) \
    asm volatile("mma.sync.aligned.m16n8k16.row.col.f32.f16.f16.f32 " \
                 "{%0,%1,%2,%3}, {%4,%5,%6,%7}, {%8,%9}, {%0,%1,%2,%3};" \
                 : "+f"((c)[0]), "+f"((c)[1]), "+f"((c)[2]), "+f"((c)[3]) \
                 : "r"(a0), "r"(a1), "r"(a2), "r"(a3), "r"(b0), "r"(b1))

// --- Kernel 1 (fused prep): blocks [0,1024) scatter W, [1024,17408) convert x.
// Scatter: CTA per (r, c-range of 64), private-owner smem accum, ascending k
// -> deterministic duplicate summation. Convert: fp32 -> fp16, 8 elems/thread.
__global__ void __launch_bounds__(256)
prep_kernel(const float* __restrict__ x,
            const float* __restrict__ values,
            const int* __restrict__ colidx) {
    const int t = threadIdx.x;
    if (blockIdx.x < 1024) {
        extern __shared__ char sws[];
        float* acc = reinterpret_cast<float*>(sws);          // 64*256 floats
        int*   cols = reinterpret_cast<int*>(sws + 65536);   // 128 ints
        const int r = blockIdx.x >> 2, clo = (blockIdx.x & 3) * 64;
        if (t < KSEL) cols[t] = colidx[r * KSEL + t];
#pragma unroll
        for (int j = 0; j < 64; j++) acc[j * 256 + t] = 0.0f;
        __syncthreads();

        const float* vb = values + (size_t)r * (KSEL * 256) + t;
#pragma unroll 4
        for (int k = 0; k < KSEL; k++) {
            const int c = cols[k] - clo;
            if ((unsigned)c < 64u) acc[c * 256 + t] += __ldg(vb + (size_t)k * 256);
        }
        __syncthreads();

        const int o = t >> 4, i = t & 15;
        uint16_t* wr = g_W + (size_t)(r * 16 + o) * INF + i;
#pragma unroll
        for (int cc = 0; cc < 64; cc++)
            wr[(clo + cc) * 16] = __half_as_ushort(__float2half_rn(acc[cc * 256 + t]));
    } else {
        size_t gt = (size_t)(blockIdx.x - 1024) * 256 + t;
        const float4* in4 = reinterpret_cast<const float4*>(x);
        float4 a = in4[2 * gt], b = in4[2 * gt + 1];
        __half2 h0 = __floats2half2_rn(a.x, a.y), h1 = __floats2half2_rn(a.z, a.w);
        __half2 h2 = __floats2half2_rn(b.x, b.y), h3 = __floats2half2_rn(b.z, b.w);
        uint4 u;
        u.x = *reinterpret_cast<uint32_t*>(&h0);
        u.y = *reinterpret_cast<uint32_t*>(&h1);
        u.z = *reinterpret_cast<uint32_t*>(&h2);
        u.w = *reinterpret_cast<uint32_t*>(&h3);
        reinterpret_cast<uint4*>(g_A)[gt] = u;
    }
}

// --- Kernel 2: decoupled warp-specialized mma.sync fp16 GEMM ---
// CTA 128x256; 16 consumer warps (4x4 of 32x64 tiles, 4/SMSP) + 2 producer
// warps (seg-major, conflict-free). 4 stages x 48 KB, per-stage mbarriers,
// NO CTA-wide barrier in the main loop.
static constexpr int STAGES      = 4;
static constexpr int A_BYTES     = 128 * 128;             // 16 KB
static constexpr int B_BYTES     = 256 * 128;             // 32 KB
static constexpr int STAGE_BYTES = A_BYTES + B_BYTES;     // 48 KB
static constexpr int GEMM_SMEM   = 1024 + STAGES * STAGE_BYTES;  // ~193 KB
static constexpr int NCHUNK      = INF / 64;              // 64

__global__ void __launch_bounds__(576, 1)
gemm_f16_kernel(float* __restrict__ out) {
    extern __shared__ char smem[];
    const uint32_t sb = smem_u32(smem);
    const uint32_t tb = sb + 1024;
    const int tid = threadIdx.x, wid = tid >> 5, lid = tid & 31;

    // full[s] = sb+16s (64 producer-thread async arrivals),
    // empty[s] = sb+16s+8 (16 consumer-warp arrivals)
    if (tid == 0) {
#pragma unroll
        for (int s = 0; s < STAGES; s++) {
            mbar_init(sb + 16 * s, 64u);
            mbar_init(sb + 16 * s + 8, 16u);
        }
    }
    __syncthreads();

    const int m0 = blockIdx.y * 128, n0 = blockIdx.x * 256;

    if (wid >= 16) {
        // ---- producers: 2 warps, 64 threads, seg-major (conflict-free) ----
        const int pt = tid - 512;               // 0..63
        const int prow = pt >> 3, pseg = pt & 7;
        // row stride 8 keeps row&7 invariant -> constant swizzled offset
        const uint32_t psw = sw128((uint32_t)prow * 128u + (uint32_t)pseg * 16u);
        const uint16_t* pa = g_A + (size_t)(m0 + prow) * INF + pseg * 8;
        const uint16_t* pb = g_W + (size_t)(n0 + prow) * INF + pseg * 8;

        int pst = 0; uint32_t pph = 1;
        for (int c = 0; c < NCHUNK; c++) {
            mbar_wait(sb + 16 * pst + 8, pph);
            const uint32_t ab = tb + (uint32_t)pst * STAGE_BYTES;
            const uint32_t bb = ab + A_BYTES;
            const int koff = c * 64;
#pragma unroll
            for (int j = 0; j < 16; j++)
                cp_async16(ab + psw + (uint32_t)j * 1024u,
                           pa + (size_t)j * 8 * INF + koff);
#pragma unroll
            for (int j = 0; j < 32; j++)
                cp_async16(bb + psw + (uint32_t)j * 1024u,
                           pb + (size_t)j * 8 * INF + koff);
            cp_async_arrive(sb + 16 * pst);
            if (++pst == STAGES) { pst = 0; pph ^= 1u; }
        }
        return;
    }

    // ---- consumers: 16 warps, 4(m) x 4(n) grid of 32x64 tiles ----
    const int wm = wid >> 2, wn = wid & 3;

    float acc[2][8][4];
#pragma unroll
    for (int mt = 0; mt < 2; mt++)
#pragma unroll
        for (int nt = 0; nt < 8; nt++)
#pragma unroll
            for (int q = 0; q < 4; q++) acc[mt][nt][q] = 0.0f;

    // sw128(row*128 + kb) = row*128 + (kb ^ ((lrow&7)<<4))
    const uint32_t lrow = (uint32_t)(lid & 15);
    const uint32_t lkb  = (uint32_t)(lid >> 4) * 16u;
    const uint32_t swb  = (lrow & 7u) << 4;
    uint32_t kbx[4];
#pragma unroll
    for (int ks = 0; ks < 4; ks++) kbx[ks] = ((uint32_t)ks * 32u + lkb) ^ swb;
    const uint32_t arow_off = ((uint32_t)(wm * 32) + lrow) * 128u;
    const uint32_t brow_off = ((uint32_t)(wn * 64) + lrow) * 128u;

    int cst = 0; uint32_t cph = 0;
    for (int c = 0; c < NCHUNK; c++) {
        mbar_wait(sb + 16 * cst, cph);

        const uint32_t ab = tb + (uint32_t)cst * STAGE_BYTES + arow_off;
        const uint32_t bb = tb + (uint32_t)cst * STAGE_BYTES + A_BYTES + brow_off;

#pragma unroll
        for (int ks = 0; ks < 4; ks++) {
            uint32_t bf[4][4];
#pragma unroll
            for (int j = 0; j < 4; j++)
                LDMATRIX_X4(bf[j][0], bf[j][1], bf[j][2], bf[j][3],
                            bb + (uint32_t)j * 2048u + kbx[ks]);
#pragma unroll
            for (int mt = 0; mt < 2; mt++) {
                uint32_t a0, a1, a2, a3;
                LDMATRIX_X4(a0, a1, a2, a3,
                            ab + (uint32_t)mt * 2048u + kbx[ks]);
#pragma unroll
                for (int j = 0; j < 4; j++) {
                    MMA16816(acc[mt][2 * j + 0], a0, a1, a2, a3, bf[j][0], bf[j][2]);
                    MMA16816(acc[mt][2 * j + 1], a0, a1, a2, a3, bf[j][1], bf[j][3]);
                }
            }
        }
        if (lid == 0) mbar_arrive(sb + 16 * cst + 8);  // release stage
        if (++cst == STAGES) { cst = 0; cph ^= 1u; }
    }

    // epilogue
    const int tq = lid >> 2, tr = lid & 3;
#pragma unroll
    for (int mt = 0; mt < 2; mt++) {
#pragma unroll
        for (int h = 0; h < 2; h++) {
            int gm = m0 + wm * 32 + mt * 16 + h * 8 + tq;
            float* row = out + (size_t)gm * NF + n0 + wn * 64 + tr * 2;
#pragma unroll
            for (int nt = 0; nt < 8; nt++) {
                float2 v;
                v.x = acc[mt][nt][h * 2 + 0];
                v.y = acc[mt][nt][h * 2 + 1];
                *reinterpret_cast<float2*>(row + nt * 8) = v;
            }
        }
    }
}

// --- pads: keep the GEMM at launch position 3 (mod 4) for ncu sampling ---
__global__ void pad_kernel() {}
__global__ void pad2_kernel() {}

extern "C" void kernel_launch(void* const* d_in, const int* in_sizes, int n_in,
                              void* d_out, int out_size) {
    const float* x      = (const float*)d_in[0];
    const float* values = (const float*)d_in[1];
    const int*   colidx = (const int*)d_in[2];
    float*       out    = (float*)d_out;

    cudaFuncSetAttribute(prep_kernel,
                         cudaFuncAttributeMaxDynamicSharedMemorySize, 66048);
    cudaFuncSetAttribute(gemm_f16_kernel,
                         cudaFuncAttributeMaxDynamicSharedMemorySize, GEMM_SMEM);

    prep_kernel<<<17408, 256, 66048>>>(x, values, colidx);
    pad_kernel<<<1, 32>>>();
    pad2_kernel<<<1, 32>>>();
    dim3 grid(NF / 256, TOKENS / 128);  // (16, 64)
    gemm_f16_kernel<<<grid, 576, GEMM_SMEM>>>(out);
}